// round 16
// baseline (speedup 1.0000x reference)
#include <cuda_runtime.h>
#include <cstdint>

#define NSTEPS 2176
#define BURN   128
#define DWALK  512
#define HMLP   1024

// ---------------- scratch (no allocations allowed) ----------------
__device__ __align__(16) float g_M [NSTEPS * DWALK];   // 0.1 * noise_t  [2176,512]
__device__ __align__(16) float g_ZD[NSTEPS * HMLP];    // M @ W1         [2176,1024]
__device__ float g_U[NSTEPS];                          // uniform u_t

// ---------------- threefry2x32 (Random123 / JAX exact) ----------------
__device__ __forceinline__ uint32_t rotl32(uint32_t x, int r) {
    return (x << r) | (x >> (32 - r));
}

__device__ __forceinline__ void threefry2x32(uint32_t k0, uint32_t k1,
                                             uint32_t c0, uint32_t c1,
                                             uint32_t& o0, uint32_t& o1) {
    uint32_t ks2 = 0x1BD11BDAu ^ k0 ^ k1;
    uint32_t x0 = c0 + k0;
    uint32_t x1 = c1 + k1;
#define TF_RND(r) { x0 += x1; x1 = rotl32(x1, r); x1 ^= x0; }
    TF_RND(13) TF_RND(15) TF_RND(26) TF_RND(6)
    x0 += k1;  x1 += ks2 + 1u;
    TF_RND(17) TF_RND(29) TF_RND(16) TF_RND(24)
    x0 += ks2; x1 += k0 + 2u;
    TF_RND(13) TF_RND(15) TF_RND(26) TF_RND(6)
    x0 += k0;  x1 += k1 + 3u;
    TF_RND(17) TF_RND(29) TF_RND(16) TF_RND(24)
    x0 += k1;  x1 += ks2 + 4u;
    TF_RND(13) TF_RND(15) TF_RND(26) TF_RND(6)
    x0 += ks2; x1 += k0 + 5u;
#undef TF_RND
    o0 = x0; o1 = x1;
}

// bits -> float in [0,1): ((b>>9)|0x3f800000) as float - 1  (JAX _uniform)
__device__ __forceinline__ float bits_to_f01(uint32_t b) {
    return __fadd_rn(__uint_as_float((b >> 9) | 0x3F800000u), -1.0f);
}

// XLA ErfInv f32 (Giles polynomial; XLA emits mul+add WITHOUT fma contraction)
__device__ __forceinline__ float erfinv_xla(float x) {
    float w = -log1pf(-__fmul_rn(x, x));
    float p;
    if (w < 5.0f) {
        w = __fadd_rn(w, -2.5f);
        p = 2.81022636e-08f;
        p = __fadd_rn(__fmul_rn(p, w), 3.43273939e-07f);
        p = __fadd_rn(__fmul_rn(p, w), -3.5233877e-06f);
        p = __fadd_rn(__fmul_rn(p, w), -4.39150654e-06f);
        p = __fadd_rn(__fmul_rn(p, w), 0.00021858087f);
        p = __fadd_rn(__fmul_rn(p, w), -0.00125372503f);
        p = __fadd_rn(__fmul_rn(p, w), -0.00417768164f);
        p = __fadd_rn(__fmul_rn(p, w), 0.246640727f);
        p = __fadd_rn(__fmul_rn(p, w), 1.50140941f);
    } else {
        w = __fadd_rn(__fsqrt_rn(w), -3.0f);
        p = -0.000200214257f;
        p = __fadd_rn(__fmul_rn(p, w), 0.000100950558f);
        p = __fadd_rn(__fmul_rn(p, w), 0.00134934322f);
        p = __fadd_rn(__fmul_rn(p, w), -0.00367342844f);
        p = __fadd_rn(__fmul_rn(p, w), 0.00573950773f);
        p = __fadd_rn(__fmul_rn(p, w), -0.0076224613f);
        p = __fadd_rn(__fmul_rn(p, w), 0.00943887047f);
        p = __fadd_rn(__fmul_rn(p, w), 1.00167406f);
        p = __fadd_rn(__fmul_rn(p, w), 2.83297682f);
    }
    return __fmul_rn(p, x);
}

// JAX normal: u = uniform(key, lo=nextafter(-1,0), hi=1); sqrt(2)*erfinv(u)
__device__ __forceinline__ float normal_from_bits(uint32_t b) {
    const float lo = -0.99999994f;  // nextafter(-1f, 0f)
    float f = bits_to_f01(b);
    float u = fmaxf(lo, __fadd_rn(__fmul_rn(f, 2.0f), lo));
    return __fmul_rn(1.4142135381698608f, erfinv_xla(u));  // float32(sqrt(2))
}

#define TANH_CLAMP 7.90531110763549805f

// XLA Tanh f32 emitter (scalar; used in one-time init paths)
__device__ __forceinline__ float tanh_xla(float x) {
    float xc = fminf(fmaxf(x, -TANH_CLAMP), TANH_CLAMP);
    float x2 = __fmul_rn(xc, xc);
    float p = -2.76076847742355e-16f;
    p = __fadd_rn(__fmul_rn(p, x2), 2.00018790482477e-13f);
    p = __fadd_rn(__fmul_rn(p, x2), -8.60467152213735e-11f);
    p = __fadd_rn(__fmul_rn(p, x2), 5.12229709037114e-08f);
    p = __fadd_rn(__fmul_rn(p, x2), 1.48572235717979e-05f);
    p = __fadd_rn(__fmul_rn(p, x2), 6.37261928875436e-04f);
    p = __fadd_rn(__fmul_rn(p, x2), 4.89352455891786e-03f);
    float num = __fmul_rn(xc, p);
    float q = 1.19825839466702e-06f;
    q = __fadd_rn(__fmul_rn(q, x2), 1.18534705686654e-04f);
    q = __fadd_rn(__fmul_rn(q, x2), 2.26843463243900e-03f);
    q = __fadd_rn(__fmul_rn(q, x2), 4.89352518554385e-03f);
    float r = __fdiv_rn(num, q);
    return (fabsf(x) < 0.0004f) ? x : r;
}

// ---------------- packed f32x2 helpers (per-lane IEEE rn => bit-exact) ----------
typedef unsigned long long u64;
__device__ __forceinline__ u64 pk2(float lo, float hi) {
    u64 r; asm("mov.b64 %0, {%1, %2};" : "=l"(r) : "f"(lo), "f"(hi)); return r;
}
__device__ __forceinline__ void upk2(u64 v, float& lo, float& hi) {
    asm("mov.b64 {%0, %1}, %2;" : "=f"(lo), "=f"(hi) : "l"(v));
}
__device__ __forceinline__ u64 mul2(u64 a, u64 b) {
    u64 r; asm("mul.rn.f32x2 %0, %1, %2;" : "=l"(r) : "l"(a), "l"(b)); return r;
}
__device__ __forceinline__ u64 add2(u64 a, u64 b) {
    u64 r; asm("add.rn.f32x2 %0, %1, %2;" : "=l"(r) : "l"(a), "l"(b)); return r;
}

// warp sum: classic 5-level shfl_down tree (redux.f32 does NOT exist on sm_103)
__device__ __forceinline__ float warp_sum(float v) {
#pragma unroll
    for (int o = 16; o > 0; o >>= 1) v += __shfl_down_sync(0xffffffffu, v, o);
    return v;   // valid on lane 0
}

struct TanhC {  // broadcast-packed coefficients, live in registers across the loop
    u64 p0, p1, p2, p3, p4, p5, p6;
    u64 q0, q1, q2, q3;
};
__device__ __forceinline__ TanhC make_tanhc() {
    TanhC c;
    c.p0 = pk2(-2.76076847742355e-16f, -2.76076847742355e-16f);
    c.p1 = pk2( 2.00018790482477e-13f,  2.00018790482477e-13f);
    c.p2 = pk2(-8.60467152213735e-11f, -8.60467152213735e-11f);
    c.p3 = pk2( 5.12229709037114e-08f,  5.12229709037114e-08f);
    c.p4 = pk2( 1.48572235717979e-05f,  1.48572235717979e-05f);
    c.p5 = pk2( 6.37261928875436e-04f,  6.37261928875436e-04f);
    c.p6 = pk2( 4.89352455891786e-03f,  4.89352455891786e-03f);
    c.q0 = pk2( 1.19825839466702e-06f,  1.19825839466702e-06f);
    c.q1 = pk2( 1.18534705686654e-04f,  1.18534705686654e-04f);
    c.q2 = pk2( 2.26843463243900e-03f,  2.26843463243900e-03f);
    c.q3 = pk2( 4.89352518554385e-03f,  4.89352518554385e-03f);
    return c;
}

// tanh_xla on two values; polynomial evaluated packed, bit-identical per lane.
// (Validated bit-exact vs scalar tanh_xla in R9/R13: identical rel_err.)
__device__ __forceinline__ void tanh2_xla(float a, float b, const TanhC& C,
                                          float& ra, float& rb) {
    float xc0 = fminf(fmaxf(a, -TANH_CLAMP), TANH_CLAMP);
    float xc1 = fminf(fmaxf(b, -TANH_CLAMP), TANH_CLAMP);
    u64 X  = pk2(xc0, xc1);
    u64 X2 = mul2(X, X);
    u64 P  = C.p0;
    P = add2(mul2(P, X2), C.p1);
    P = add2(mul2(P, X2), C.p2);
    P = add2(mul2(P, X2), C.p3);
    P = add2(mul2(P, X2), C.p4);
    P = add2(mul2(P, X2), C.p5);
    P = add2(mul2(P, X2), C.p6);
    u64 NUM = mul2(X, P);
    u64 Q = C.q0;
    Q = add2(mul2(Q, X2), C.q1);
    Q = add2(mul2(Q, X2), C.q2);
    Q = add2(mul2(Q, X2), C.q3);
    float n0, n1, q0, q1;
    upk2(NUM, n0, n1);
    upk2(Q,   q0, q1);
    float r0 = __fdiv_rn(n0, q0);
    float r1 = __fdiv_rn(n1, q1);
    ra = (fabsf(a) < 0.0004f) ? a : r0;
    rb = (fabsf(b) < 0.0004f) ? b : r1;
}

// ---------------- kernel 1: per-step keys, uniforms, normals ----------------
// jax_threefry_partitionable=True semantics (verified passing R3/R6/R9/R13):
//   split(key, n)[t]             = output pair of TF(key, (0, t))
//   random_bits(key,32,shape)[i] = o0 ^ o1 of TF(key, (0, i))
__global__ void gen_kernel() {
    int t = blockIdx.x;
    int i = threadIdx.x;  // 0..511

    uint32_t kt0, kt1, kn0, kn1;
    threefry2x32(0u, 1u, 0u, (uint32_t)t, kt0, kt1);
    threefry2x32(kt0, kt1, 0u, 0u, kn0, kn1);

    if (i == 0) {
        uint32_t ku0, ku1, ua, ub;
        threefry2x32(kt0, kt1, 0u, 1u, ku0, ku1);
        threefry2x32(ku0, ku1, 0u, 0u, ua, ub);
        g_U[t] = bits_to_f01(ua ^ ub);
    }

    uint32_t r0, r1;
    threefry2x32(kn0, kn1, 0u, (uint32_t)i, r0, r1);
    g_M[t * DWALK + i] = __fmul_rn(normal_from_bits(r0 ^ r1), 0.1f);
}

// ---------------- kernel 2: fp32 SGEMM  ZD = M @ W1 ----------------
// 128x128x8 tile, 256 threads, 8x8 per-thread microtile. 136 blocks ~ 1 wave.
__global__ void __launch_bounds__(256) gemm_kernel(const float* __restrict__ W1) {
    __shared__ float As[8][128];
    __shared__ float Bs[8][128];

    int tid = threadIdx.x;
    int tx = tid & 15;
    int ty = tid >> 4;
    int rowBase = blockIdx.y * 128;
    int colBase = blockIdx.x * 128;

    int aRow = tid >> 1;
    int aK   = (tid & 1) * 4;
    int bK   = tid >> 5;
    int bCol = (tid & 31) * 4;

    float acc[8][8] = {{0.f}};

    for (int k0 = 0; k0 < 512; k0 += 8) {
        float4 av = *reinterpret_cast<const float4*>(&g_M[(rowBase + aRow) * 512 + k0 + aK]);
        float4 bv = *reinterpret_cast<const float4*>(&W1[(k0 + bK) * 1024 + colBase + bCol]);
        As[aK + 0][aRow] = av.x;
        As[aK + 1][aRow] = av.y;
        As[aK + 2][aRow] = av.z;
        As[aK + 3][aRow] = av.w;
        *reinterpret_cast<float4*>(&Bs[bK][bCol]) = bv;
        __syncthreads();
#pragma unroll
        for (int k = 0; k < 8; k++) {
            float4 a0 = *reinterpret_cast<float4*>(&As[k][ty * 8]);
            float4 a1 = *reinterpret_cast<float4*>(&As[k][ty * 8 + 4]);
            float4 b0 = *reinterpret_cast<float4*>(&Bs[k][tx * 8]);
            float4 b1 = *reinterpret_cast<float4*>(&Bs[k][tx * 8 + 4]);
            float ar[8] = {a0.x, a0.y, a0.z, a0.w, a1.x, a1.y, a1.z, a1.w};
            float br[8] = {b0.x, b0.y, b0.z, b0.w, b1.x, b1.y, b1.z, b1.w};
#pragma unroll
            for (int i = 0; i < 8; i++)
#pragma unroll
                for (int j = 0; j < 8; j++)
                    acc[i][j] = fmaf(ar[i], br[j], acc[i][j]);
        }
        __syncthreads();
    }
#pragma unroll
    for (int i = 0; i < 8; i++) {
        int r = rowBase + ty * 8 + i;
        *reinterpret_cast<float4*>(&g_ZD[r * 1024 + colBase + tx * 8]) =
            make_float4(acc[i][0], acc[i][1], acc[i][2], acc[i][3]);
        *reinterpret_cast<float4*>(&g_ZD[r * 1024 + colBase + tx * 8 + 4]) =
            make_float4(acc[i][4], acc[i][5], acc[i][6], acc[i][7]);
    }
}

// ---------------- kernel 3: sequential MH chain (1 CTA, 128 threads) ------------
// Serial-latency optimized: 4 warps (1/SMSP), 8 hidden units + 4 walker dims per
// thread, shfl warp sum, 4-partial cross-warp combine, prefetch distance 2,
// decision via multiply (u*den < p_new) instead of divide.
__global__ void __launch_bounds__(128, 1)
chain_kernel(const float* __restrict__ x0, const float* __restrict__ W1,
             const float* __restrict__ b1, const float* __restrict__ W2,
             const float* __restrict__ b2, float* __restrict__ out) {
    __shared__ float s_x0[DWALK];
    __shared__ __align__(16) float s_part[2][4];

    int tid  = threadIdx.x;          // 0..127
    int lane = tid & 31;
    int wid  = tid >> 5;             // 0..3

    for (int i = tid; i < DWALK; i += 128) s_x0[i] = x0[i];
    __syncthreads();

    const TanhC TC = make_tanhc();

    // z_j = dot(x0, W1[:, 8*tid + j]), j = 0..7
    float z0 = 0.f, z1 = 0.f, z2 = 0.f, z3 = 0.f;
    float z4 = 0.f, z5 = 0.f, z6 = 0.f, z7 = 0.f;
    {
        const float4* w1p = reinterpret_cast<const float4*>(W1) + 2 * tid; // row stride 256
#pragma unroll 4
        for (int k = 0; k < DWALK; k++) {
            float xv = s_x0[k];
            float4 wa = w1p[(size_t)k * 256];
            float4 wb = w1p[(size_t)k * 256 + 1];
            z0 = fmaf(xv, wa.x, z0); z1 = fmaf(xv, wa.y, z1);
            z2 = fmaf(xv, wa.z, z2); z3 = fmaf(xv, wa.w, z3);
            z4 = fmaf(xv, wb.x, z4); z5 = fmaf(xv, wb.y, z5);
            z6 = fmaf(xv, wb.z, z6); z7 = fmaf(xv, wb.w, z7);
        }
    }

    float4 b1a = *(reinterpret_cast<const float4*>(b1) + 2 * tid);
    float4 b1b = *(reinterpret_cast<const float4*>(b1) + 2 * tid + 1);
    float4 w2a = *(reinterpret_cast<const float4*>(W2) + 2 * tid);
    float4 w2b = *(reinterpret_cast<const float4*>(W2) + 2 * tid + 1);
    float  b2v = b2[0];

    // walker dims 4*tid..4*tid+3, packed as 2 u64
    u64 X0, X1;
    {
        float4 xv = *(reinterpret_cast<const float4*>(x0) + tid);
        X0 = pk2(xv.x, xv.y);
        X1 = pk2(xv.z, xv.w);
    }

    // packed pre-activation state & biases
    u64 Z_0 = pk2(z0, z1), Z_1 = pk2(z2, z3), Z_2 = pk2(z4, z5), Z_3 = pk2(z6, z7);
    u64 B0 = pk2(b1a.x, b1a.y), B1_ = pk2(b1a.z, b1a.w);
    u64 B2_ = pk2(b1b.x, b1b.y), B3 = pk2(b1b.z, b1b.w);

    // fixed-order per-thread pv over 8 units
    auto pv8 = [&](float h0, float h1, float h2, float h3,
                   float h4, float h5, float h6, float h7) -> float {
        float a = __fadd_rn(__fadd_rn(__fmul_rn(h0, w2a.x), __fmul_rn(h1, w2a.y)),
                            __fadd_rn(__fmul_rn(h2, w2a.z), __fmul_rn(h3, w2a.w)));
        float b = __fadd_rn(__fadd_rn(__fmul_rn(h4, w2b.x), __fmul_rn(h5, w2b.y)),
                            __fadd_rn(__fmul_rn(h6, w2b.z), __fmul_rn(h7, w2b.w)));
        return __fadd_rn(a, b);
    };
    // fixed-order sum of 4 warp partials
    auto tree4 = [&](const float* sp) -> float {
        float4 q = *reinterpret_cast<const float4*>(sp);
        return __fadd_rn(__fadd_rn(q.x, q.y), __fadd_rn(q.z, q.w));
    };

    // ---- p_old = psi2(x0) ----
    float den;
    {
        float h0 = tanh_xla(__fadd_rn(z0, b1a.x));
        float h1 = tanh_xla(__fadd_rn(z1, b1a.y));
        float h2 = tanh_xla(__fadd_rn(z2, b1a.z));
        float h3 = tanh_xla(__fadd_rn(z3, b1a.w));
        float h4 = tanh_xla(__fadd_rn(z4, b1b.x));
        float h5 = tanh_xla(__fadd_rn(z5, b1b.y));
        float h6 = tanh_xla(__fadd_rn(z6, b1b.z));
        float h7 = tanh_xla(__fadd_rn(z7, b1b.w));
        float pv = pv8(h0, h1, h2, h3, h4, h5, h6, h7);
        float ws = warp_sum(pv);
        if (lane == 0) s_part[1][wid] = ws;
        __syncthreads();
        float mdl = __fadd_rn(tree4(s_part[1]), b2v);
        den = __fadd_rn(__fmul_rn(mdl, mdl), 1e-12f);
    }
    __syncthreads();   // all reads of s_part[1] done before loop step 1 rewrites it

    // row pointers (t-indexed only, accept-independent)
    const ulonglong2* pZD = reinterpret_cast<const ulonglong2*>(g_ZD) + 2 * tid; // row 256
    const ulonglong2* pM  = reinterpret_cast<const ulonglong2*>(g_M) + tid;      // row 128
    ulonglong2*       pO  = reinterpret_cast<ulonglong2*>(out) + tid;            // row 128

    // prefetch slots: A = even steps, B = odd steps (distance-2 pipeline)
    ulonglong2 ZAl = pZD[0], ZAh = pZD[1];
    ulonglong2 MA  = pM[0];
    float      UA  = g_U[0];
    ulonglong2 ZBl = pZD[256], ZBh = pZD[257];
    ulonglong2 MB  = pM[128];
    float      UB  = g_U[1];

#define CHAIN_STEP(T, ZL, ZH, MV, UV)                                              \
    {                                                                              \
        u64 m0 = (MV).x, m1 = (MV).y;                                              \
        float u_cur = (UV);                                                        \
        u64 ZN0 = add2(Z_0, (ZL).x), ZN1 = add2(Z_1, (ZL).y);                      \
        u64 ZN2 = add2(Z_2, (ZH).x), ZN3 = add2(Z_3, (ZH).y);                      \
        /* prefetch T+2 into this slot (before barrier; independent of accs) */    \
        if ((T) + 2 < NSTEPS) {                                                    \
            (ZL) = pZD[(size_t)((T) + 2) * 256];                                   \
            (ZH) = pZD[(size_t)((T) + 2) * 256 + 1];                               \
            (MV) = pM [(size_t)((T) + 2) * 128];                                   \
            (UV) = g_U[(T) + 2];                                                   \
        }                                                                          \
        float a0, a1, a2, a3, a4, a5, a6, a7;                                      \
        upk2(add2(ZN0, B0),  a0, a1);                                              \
        upk2(add2(ZN1, B1_), a2, a3);                                              \
        upk2(add2(ZN2, B2_), a4, a5);                                              \
        upk2(add2(ZN3, B3),  a6, a7);                                              \
        float h0, h1, h2, h3, h4, h5, h6, h7;                                      \
        tanh2_xla(a0, a1, TC, h0, h1);                                             \
        tanh2_xla(a2, a3, TC, h2, h3);                                             \
        tanh2_xla(a4, a5, TC, h4, h5);                                             \
        tanh2_xla(a6, a7, TC, h6, h7);                                             \
        float pv = pv8(h0, h1, h2, h3, h4, h5, h6, h7);                            \
        float ws = warp_sum(pv);                                                   \
        if (lane == 0) s_part[(T) & 1][wid] = ws;                                  \
        __syncthreads();                                                           \
        float mdl   = __fadd_rn(tree4(s_part[(T) & 1]), b2v);                      \
        float p_new = __fmul_rn(mdl, mdl);                                         \
        /* u < p_new/den (den>0)  <=>  u*den < p_new  (mul replaces div) */        \
        bool  acc   = (__fmul_rn(u_cur, den) < p_new);                             \
        if (acc) {                                                                 \
            den = __fadd_rn(p_new, 1e-12f);                                        \
            Z_0 = ZN0; Z_1 = ZN1; Z_2 = ZN2; Z_3 = ZN3;                            \
            X0 = add2(X0, m0); X1 = add2(X1, m1);                                  \
        }                                                                          \
        if ((T) >= BURN) pO[(size_t)((T) - BURN) * 128] = make_ulonglong2(X0, X1); \
    }

    for (int t = 0; t < NSTEPS; t += 2) {
        CHAIN_STEP(t,     ZAl, ZAh, MA, UA)
        CHAIN_STEP(t + 1, ZBl, ZBh, MB, UB)
    }
#undef CHAIN_STEP
}

// ---------------- launch ----------------
extern "C" void kernel_launch(void* const* d_in, const int* in_sizes, int n_in,
                              void* d_out, int out_size) {
    const float* x0 = (const float*)d_in[0];
    const float* W1 = (const float*)d_in[1];
    const float* b1 = (const float*)d_in[2];
    const float* W2 = (const float*)d_in[3];
    const float* b2 = (const float*)d_in[4];
    float* out = (float*)d_out;

    gen_kernel<<<NSTEPS, DWALK>>>();
    gemm_kernel<<<dim3(HMLP / 128, NSTEPS / 128), 256>>>(W1);
    chain_kernel<<<1, 128>>>(x0, W1, b1, W2, b2, out);
}